// round 3
// baseline (speedup 1.0000x reference)
#include <cuda_runtime.h>
#include <cstdint>
#include <cstddef>

typedef unsigned long long ull;

#define BB 32
#define TT 1024
#define HH 512
#define GG 2048
#define NCTA 128

// ---------------- device scratch (allocations are forbidden) ----------------
__device__ __align__(16) float g_xp[(size_t)TT * GG * BB];   // 256 MB x_proj[t][g][b]
__device__ __align__(16) float g_hbuf[2][HH * BB];           // ping-pong h[k][b]
__device__ __align__(128) unsigned g_flags[NCTA * 8];        // 32B-strided per-CTA flags

// ---------------- f32x2 helpers (FFMA2 is PTX-only) ----------------
__device__ __forceinline__ ull ffma2(ull a, ull b, ull c) {
    ull d;
    asm("fma.rn.f32x2 %0, %1, %2, %3;" : "=l"(d) : "l"(a), "l"(b), "l"(c));
    return d;
}
__device__ __forceinline__ ull fadd2(ull a, ull b) {
    ull d;
    asm("add.rn.f32x2 %0, %1, %2;" : "=l"(d) : "l"(a), "l"(b));
    return d;
}
__device__ __forceinline__ ull pack2(float x, float y) {
    ull d;
    asm("mov.b64 %0, {%1, %2};" : "=l"(d) : "f"(x), "f"(y));
    return d;
}
__device__ __forceinline__ float sigm(float x) { return 1.0f / (1.0f + __expf(-x)); }

__device__ __forceinline__ unsigned smem_u32(const void* p) {
    unsigned a;
    asm("{ .reg .u64 t; cvta.to.shared.u64 t, %1; cvt.u32.u64 %0, t; }" : "=r"(a) : "l"(p));
    return a;
}
__device__ __forceinline__ void cp_async16(unsigned dst, const void* src) {
    asm volatile("cp.async.cg.shared.global [%0], [%1], 16;" :: "r"(dst), "l"(src));
}
__device__ __forceinline__ void cp_async_wait_all() {
    asm volatile("cp.async.commit_group;\ncp.async.wait_group 0;" ::: "memory");
}

// =========================================================================
// Kernel 1: x_proj[t][g][b] = sum_c src[b][t][c]*W_ih[g][c] + b_ih[g]+b_hh[g]
// grid (8, 256). CTA(0,0) also zeroes g_hbuf + g_flags (stream order covers
// the lstm kernel's dependency on them).
// =========================================================================
#define WPITCH 68   // 64 + 4 pad (words)
#define XPITCH 132  // 128 + 4 pad (words)

__global__ __launch_bounds__(512, 1) void xproj_kernel(
    const float* __restrict__ src, const float* __restrict__ Wih,
    const float* __restrict__ bih, const float* __restrict__ bhh)
{
    extern __shared__ float sm[];
    float* w_s = sm;                  // [256][WPITCH]
    float* x_s = sm + 256 * WPITCH;   // [64][XPITCH]  x transposed: [c][n]

    const int tid = threadIdx.x;
    if (blockIdx.x == 0 && blockIdx.y == 0) {
        for (int i = tid; i < 2 * HH * BB; i += 512) g_hbuf[0][i] = 0.0f;  // both buffers
        if (tid < NCTA * 8) g_flags[tid] = 0u;
    }

    const int g0  = blockIdx.x * 256;
    const int t0  = blockIdx.y * 4;
    const int ni  = tid & 15;    // n tile: ni*8 .. ni*8+7
    const int gi  = tid >> 4;    // g tile: gi*8 .. gi*8+7

    ull acc[32];
#pragma unroll
    for (int i = 0; i < 32; i++) acc[i] = 0ull;

    for (int kc = 0; kc < 8; kc++) {
        const int c0 = kc * 64;
#pragma unroll
        for (int i = 0; i < 8; i++) {
            int fq = tid + i * 512;
            int g = fq >> 4, cq = fq & 15;
            float4 wv = *(const float4*)(Wih + (size_t)(g0 + g) * HH + c0 + cq * 4);
            *(float4*)(w_s + g * WPITCH + cq * 4) = wv;
        }
#pragma unroll
        for (int i = 0; i < 4; i++) {
            int fq = tid + i * 512;
            int n = fq & 127, cq = fq >> 7;
            int b = n & 31, ti = n >> 5;
            float4 xv = *(const float4*)(src + ((size_t)b * TT + (t0 + ti)) * HH + c0 + cq * 4);
            x_s[(cq * 4 + 0) * XPITCH + n] = xv.x;
            x_s[(cq * 4 + 1) * XPITCH + n] = xv.y;
            x_s[(cq * 4 + 2) * XPITCH + n] = xv.z;
            x_s[(cq * 4 + 3) * XPITCH + n] = xv.w;
        }
        __syncthreads();

#pragma unroll 4
        for (int k = 0; k < 64; k++) {
            ulonglong2 xa = *(const ulonglong2*)(x_s + k * XPITCH + ni * 8);
            ulonglong2 xb = *(const ulonglong2*)(x_s + k * XPITCH + ni * 8 + 4);
            const float* wr = w_s + (gi * 8) * WPITCH + k;
#pragma unroll
            for (int i = 0; i < 8; i++) {
                float w = wr[i * WPITCH];
                ull w2 = pack2(w, w);
                acc[i * 4 + 0] = ffma2(xa.x, w2, acc[i * 4 + 0]);
                acc[i * 4 + 1] = ffma2(xa.y, w2, acc[i * 4 + 1]);
                acc[i * 4 + 2] = ffma2(xb.x, w2, acc[i * 4 + 2]);
                acc[i * 4 + 3] = ffma2(xb.y, w2, acc[i * 4 + 3]);
            }
        }
        __syncthreads();
    }

#pragma unroll
    for (int i = 0; i < 8; i++) {
        int g = g0 + gi * 8 + i;
        float bs = bih[g] + bhh[g];
        ull b2 = pack2(bs, bs);
#pragma unroll
        for (int p = 0; p < 4; p++) {
            int n = ni * 8 + 2 * p;
            int t = t0 + (n >> 5), b = n & 31;
            ull v = fadd2(acc[i * 4 + p], b2);
            *(ull*)(g_xp + ((size_t)t * GG + g) * BB + b) = v;
        }
    }
}

// =========================================================================
// Kernel 2: persistent LSTM recurrence. 128 CTAs x 256 threads.
// Flag-array grid barrier (no atomics): CTA i release-stores g_flags[i*8]=t+1;
// every CTA's threads 0..127 acquire-poll one flag each.
// h staged via cp.async (L1-bypassing, latency-batched).
// =========================================================================
#define RED_PITCH 34

__global__ __launch_bounds__(256, 1) void lstm_kernel(
    const int* __restrict__ lengths, const float* __restrict__ Whh,
    float* __restrict__ out)
{
    extern __shared__ float sm[];
    float* h_s = sm;                         // [512][32] swizzled, 64 KB
    float* red = sm + HH * BB;               // [32 kc][16 rows][RED_PITCH]
    float* ho  = red + 32 * 16 * RED_PITCH;  // [32 b][4 h]

    const int tid = threadIdx.x;
    const int cta = blockIdx.x;
    const int rp  = tid & 7;
    const int kc  = tid >> 3;
    const int gateA = rp >> 2, hofA = rp & 3;
    const int growA = gateA * HH + cta * 4 + hofA;
    const int growB = growA + 2 * HH;

    // preload W_hh slices, packed {w,w}
    ull w2a[16], w2b[16];
#pragma unroll
    for (int q = 0; q < 4; q++) {
        float4 wa = *(const float4*)(Whh + (size_t)growA * HH + kc * 16 + q * 4);
        float4 wb = *(const float4*)(Whh + (size_t)growB * HH + kc * 16 + q * 4);
        w2a[q * 4 + 0] = pack2(wa.x, wa.x); w2a[q * 4 + 1] = pack2(wa.y, wa.y);
        w2a[q * 4 + 2] = pack2(wa.z, wa.z); w2a[q * 4 + 3] = pack2(wa.w, wa.w);
        w2b[q * 4 + 0] = pack2(wb.x, wb.x); w2b[q * 4 + 1] = pack2(wb.y, wb.y);
        w2b[q * 4 + 2] = pack2(wb.z, wb.z); w2b[q * 4 + 3] = pack2(wb.w, wb.w);
    }

    const int ub = tid & 31, uh = tid >> 5;  // updater mapping (tid < 128)
    int   len = 0;
    float c_r = 0.0f, h_r = 0.0f;
    if (tid < 128) len = lengths[ub];

    // precompute staging addresses
    const unsigned h_s_base = smem_u32(h_s);
    const unsigned my_flag_sm = 0;  // unused placeholder

    for (int t = 0; t < TT; t++) {
        const int p = t & 1;

        // prefetch this step's x_proj gates BEFORE the barrier spin
        float xg0 = 0.f, xg1 = 0.f, xg2 = 0.f, xg3 = 0.f;
        if (tid < 128) {
            const float* xp = g_xp + ((size_t)t * GG + cta * 4 + uh) * BB + ub;
            xg0 = xp[0 * HH * BB];
            xg1 = xp[1 * HH * BB];
            xg2 = xp[2 * HH * BB];
            xg3 = xp[3 * HH * BB];
        }

        // ---- grid barrier wait: all flags >= t (t=0 trivially satisfied)
        if (t > 0 && tid < 128) {
            const unsigned* f = &g_flags[tid * 8];
            unsigned v;
            do {
                asm volatile("ld.acquire.gpu.u32 %0, [%1];" : "=r"(v) : "l"(f) : "memory");
            } while (v < (unsigned)t);
        }
        __syncthreads();

        // ---- stage h[k][b] -> swizzled smem via cp.async
        const float* hsrc = g_hbuf[p];
#pragma unroll
        for (int i = 0; i < 16; i++) {
            int fq = tid + i * 256;          // float4 index 0..4095
            int k = fq >> 3, c = fq & 7;
            int chunk = (c + (k >> 4)) & 7;
            cp_async16(h_s_base + (unsigned)(k * 32 + chunk * 4) * 4u,
                       hsrc + (size_t)fq * 4);
        }
        cp_async_wait_all();
        __syncthreads();

        // ---- matmul partials: 16 k x 2 rows x 32 b per thread
        ull accA[16], accB[16];
#pragma unroll
        for (int i = 0; i < 16; i++) { accA[i] = 0ull; accB[i] = 0ull; }
        const int sw = kc & 7;
#pragma unroll 4
        for (int j = 0; j < 16; j++) {
            const float* hrow = h_s + (kc * 16 + j) * 32;
            ull wa = w2a[j], wb = w2b[j];
#pragma unroll
            for (int c = 0; c < 8; c++) {
                int chunk = (c + sw) & 7;
                ulonglong2 hv = *(const ulonglong2*)(hrow + chunk * 4);
                accA[2 * c]     = ffma2(hv.x, wa, accA[2 * c]);
                accA[2 * c + 1] = ffma2(hv.y, wa, accA[2 * c + 1]);
                accB[2 * c]     = ffma2(hv.x, wb, accB[2 * c]);
                accB[2 * c + 1] = ffma2(hv.y, wb, accB[2 * c + 1]);
            }
        }
        {
            ull* rA = (ull*)(red + (size_t)(kc * 16 + rp) * RED_PITCH);
            ull* rB = (ull*)(red + (size_t)(kc * 16 + rp + 8) * RED_PITCH);
#pragma unroll
            for (int i = 0; i < 16; i++) { rA[i] = accA[i]; rB[i] = accB[i]; }
        }
        __syncthreads();

        // ---- updaters: reduce over 32 k-chunks, apply gates, publish h
        if (tid < 128) {
            float v[4];
#pragma unroll
            for (int gt = 0; gt < 4; gt++) {
                int row = gt * 4 + uh;
                float s0 = 0.f, s1 = 0.f, s2 = 0.f, s3 = 0.f;
#pragma unroll
                for (int q = 0; q < 8; q++) {
                    s0 += red[((q * 4 + 0) * 16 + row) * RED_PITCH + ub];
                    s1 += red[((q * 4 + 1) * 16 + row) * RED_PITCH + ub];
                    s2 += red[((q * 4 + 2) * 16 + row) * RED_PITCH + ub];
                    s3 += red[((q * 4 + 3) * 16 + row) * RED_PITCH + ub];
                }
                v[gt] = (s0 + s1) + (s2 + s3);
            }
            float gi_ = sigm(xg0 + v[0]);
            float gf  = sigm(xg1 + v[1]);
            float gg  = tanhf(xg2 + v[2]);
            float go  = sigm(xg3 + v[3]);
            float c_new = gf * c_r + gi_ * gg;
            float h_new = go * tanhf(c_new);
            bool valid = (t < len);
            if (valid) { c_r = c_new; h_r = h_new; }
            ho[ub * 4 + uh] = valid ? h_new : 0.0f;
            g_hbuf[1 - p][(cta * 4 + uh) * BB + ub] = h_r;
        }
        __syncthreads();

        // ---- release our flag FIRST (critical path), then store output
        if (tid == 0) {
            asm volatile("st.release.gpu.u32 [%0], %1;"
                         :: "l"(&g_flags[cta * 8]), "r"((unsigned)(t + 1)) : "memory");
        }
        if (tid < 32) {
            float4 o4 = *(const float4*)(ho + tid * 4);
            *(float4*)(out + ((size_t)t * BB + tid) * HH + cta * 4) = o4;
        }
    }

    // final hT, cT
    if (tid < 128) {
        size_t base = (size_t)TT * BB * HH;
        out[base + (size_t)ub * HH + cta * 4 + uh] = h_r;
        out[base + (size_t)BB * HH + (size_t)ub * HH + cta * 4 + uh] = c_r;
    }
}

// =========================================================================
extern "C" void kernel_launch(void* const* d_in, const int* in_sizes, int n_in,
                              void* d_out, int out_size) {
    const float* src  = (const float*)d_in[0];
    const int*   lens = (const int*)d_in[1];
    const float* Wih  = (const float*)d_in[2];
    const float* Whh  = (const float*)d_in[3];
    const float* bih  = (const float*)d_in[4];
    const float* bhh  = (const float*)d_in[5];
    float* out = (float*)d_out;

    const int smem_xproj = (256 * WPITCH + 64 * XPITCH) * 4;
    const int smem_lstm  = (HH * BB + 32 * 16 * RED_PITCH + 128) * 4;
    cudaFuncSetAttribute(xproj_kernel, cudaFuncAttributeMaxDynamicSharedMemorySize, smem_xproj);
    cudaFuncSetAttribute(lstm_kernel,  cudaFuncAttributeMaxDynamicSharedMemorySize, smem_lstm);

    dim3 grid(8, 256);
    xproj_kernel<<<grid, 512, smem_xproj>>>(src, Wih, bih, bhh);
    lstm_kernel<<<NCTA, 256, smem_lstm>>>(lens, Whh, out);
}

// round 5
// speedup vs baseline: 1.4829x; 1.4829x over previous
#include <cuda_runtime.h>
#include <cuda_bf16.h>
#include <cstdint>
#include <cstddef>

typedef unsigned long long ull;
typedef unsigned int u32;

#define BB 32
#define TT 1024
#define HH 512
#define GG 2048
#define NCTA 128
#define PITCH_W 260              // words per h-image row (512 bf16 = 256 + 4 pad)
#define PLANE_B (32 * PITCH_W * 4)   // 33280 bytes per plane

// ---------------- device scratch (allocations are forbidden) ----------------
__device__ __align__(16) float g_xp[(size_t)TT * GG * BB];          // 256 MB x_proj[t][g][b]
__device__ __align__(16) unsigned char g_h[2][2][PLANE_B];          // [phase][hi/lo][b][k] bf16
__device__ __align__(128) unsigned g_flags[NCTA * 8];               // 32B-strided flags

// ---------------- f32x2 helpers (FFMA2 is PTX-only) ----------------
__device__ __forceinline__ ull ffma2(ull a, ull b, ull c) {
    ull d; asm("fma.rn.f32x2 %0, %1, %2, %3;" : "=l"(d) : "l"(a), "l"(b), "l"(c)); return d;
}
__device__ __forceinline__ ull fadd2(ull a, ull b) {
    ull d; asm("add.rn.f32x2 %0, %1, %2;" : "=l"(d) : "l"(a), "l"(b)); return d;
}
__device__ __forceinline__ ull pack2(float x, float y) {
    ull d; asm("mov.b64 %0, {%1, %2};" : "=l"(d) : "f"(x), "f"(y)); return d;
}
__device__ __forceinline__ float sigm(float x) { return __fdividef(1.0f, 1.0f + __expf(-x)); }
__device__ __forceinline__ float tanh_(float x) { return 1.0f - __fdividef(2.0f, __expf(2.0f * x) + 1.0f); }

__device__ __forceinline__ u32 smem_u32(const void* p) {
    u32 a; asm("{ .reg .u64 t; cvta.to.shared.u64 t, %1; cvt.u32.u64 %0, t; }" : "=r"(a) : "l"(p)); return a;
}
__device__ __forceinline__ void cp_async16(u32 dst, const void* src) {
    asm volatile("cp.async.cg.shared.global [%0], [%1], 16;" :: "r"(dst), "l"(src));
}

__device__ __forceinline__ u32 pack_bf2(float a, float b) {
    return (u32)__bfloat16_as_ushort(__float2bfloat16(a))
         | ((u32)__bfloat16_as_ushort(__float2bfloat16(b)) << 16);
}

// mma.sync m16n8k16 row.col f32.bf16.bf16.f32 (baseline sm_80+, OK at .target sm_103)
__device__ __forceinline__ void mma16816(float& c0, float& c1, float& c2, float& c3,
                                         u32 a0, u32 a1, u32 a2, u32 a3, u32 b0, u32 b1) {
    asm volatile(
        "mma.sync.aligned.m16n8k16.row.col.f32.bf16.bf16.f32 "
        "{%0,%1,%2,%3}, {%4,%5,%6,%7}, {%8,%9}, {%0,%1,%2,%3};"
        : "+f"(c0), "+f"(c1), "+f"(c2), "+f"(c3)
        : "r"(a0), "r"(a1), "r"(a2), "r"(a3), "r"(b0), "r"(b1));
}

// =========================================================================
// Kernel 1: x_proj (FFMA2 GEMM) + zero g_h / g_flags from CTA(0,0)
// =========================================================================
#define WPITCH 68
#define XPITCH 132

__global__ __launch_bounds__(512, 1) void xproj_kernel(
    const float* __restrict__ src, const float* __restrict__ Wih,
    const float* __restrict__ bih, const float* __restrict__ bhh)
{
    extern __shared__ float sm[];
    float* w_s = sm;
    float* x_s = sm + 256 * WPITCH;

    const int tid = threadIdx.x;
    if (blockIdx.x == 0 && blockIdx.y == 0) {
        uint4 z = {0, 0, 0, 0};
        const int n16 = (2 * 2 * PLANE_B) / 16;   // 8320
        for (int i = tid; i < n16; i += 512) ((uint4*)g_h)[i] = z;
        for (int i = tid; i < NCTA * 8; i += 512) g_flags[i] = 0u;
    }

    const int g0 = blockIdx.x * 256;
    const int t0 = blockIdx.y * 4;
    const int ni = tid & 15;
    const int gi = tid >> 4;

    ull acc[32];
#pragma unroll
    for (int i = 0; i < 32; i++) acc[i] = 0ull;

    for (int kc = 0; kc < 8; kc++) {
        const int c0 = kc * 64;
#pragma unroll
        for (int i = 0; i < 8; i++) {
            int fq = tid + i * 512;
            int g = fq >> 4, cq = fq & 15;
            float4 wv = *(const float4*)(Wih + (size_t)(g0 + g) * HH + c0 + cq * 4);
            *(float4*)(w_s + g * WPITCH + cq * 4) = wv;
        }
#pragma unroll
        for (int i = 0; i < 4; i++) {
            int fq = tid + i * 512;
            int n = fq & 127, cq = fq >> 7;
            int b = n & 31, ti = n >> 5;
            float4 xv = *(const float4*)(src + ((size_t)b * TT + (t0 + ti)) * HH + c0 + cq * 4);
            x_s[(cq * 4 + 0) * XPITCH + n] = xv.x;
            x_s[(cq * 4 + 1) * XPITCH + n] = xv.y;
            x_s[(cq * 4 + 2) * XPITCH + n] = xv.z;
            x_s[(cq * 4 + 3) * XPITCH + n] = xv.w;
        }
        __syncthreads();

#pragma unroll 4
        for (int k = 0; k < 64; k++) {
            ulonglong2 xa = *(const ulonglong2*)(x_s + k * XPITCH + ni * 8);
            ulonglong2 xb = *(const ulonglong2*)(x_s + k * XPITCH + ni * 8 + 4);
            const float* wr = w_s + (gi * 8) * WPITCH + k;
#pragma unroll
            for (int i = 0; i < 8; i++) {
                float w = wr[i * WPITCH];
                ull w2 = pack2(w, w);
                acc[i * 4 + 0] = ffma2(xa.x, w2, acc[i * 4 + 0]);
                acc[i * 4 + 1] = ffma2(xa.y, w2, acc[i * 4 + 1]);
                acc[i * 4 + 2] = ffma2(xb.x, w2, acc[i * 4 + 2]);
                acc[i * 4 + 3] = ffma2(xb.y, w2, acc[i * 4 + 3]);
            }
        }
        __syncthreads();
    }

#pragma unroll
    for (int i = 0; i < 8; i++) {
        int g = g0 + gi * 8 + i;
        float bs = bih[g] + bhh[g];
        ull b2 = pack2(bs, bs);
#pragma unroll
        for (int p = 0; p < 4; p++) {
            int n = ni * 8 + 2 * p;
            int t = t0 + (n >> 5), b = n & 31;
            ull v = fadd2(acc[i * 4 + p], b2);
            *(ull*)(g_xp + ((size_t)t * GG + g) * BB + b) = v;
        }
    }
}

// =========================================================================
// Kernel 2: HMMA (mma.sync bf16, 3-term split) recurrence. 128 CTAs x 256 thr.
// CTA owns 16 gate rows m = gate*4 + unit, units = cta*4..+4.  M=16 N=32 K=512.
// Warp w owns K-chunk [w*64, w*64+64); W fragments live in registers.
// =========================================================================
#define SM_HI   0
#define SM_LO   PLANE_B
#define SM_RED  (2 * PLANE_B)                 // red[8][16][40] floats
#define SM_TOT  (2 * PLANE_B + 8 * 16 * 40 * 4)

__global__ __launch_bounds__(256, 1) void lstm_kernel(
    const int* __restrict__ lengths, const float* __restrict__ Whh,
    float* __restrict__ out)
{
    extern __shared__ char smc[];
    const u32 smem_base = smem_u32(smc);
    const u32* hi_w = (const u32*)(smc + SM_HI);
    const u32* lo_w = (const u32*)(smc + SM_LO);
    float* red_s = (float*)(smc + SM_RED);

    const int tid  = threadIdx.x;
    const int cta  = blockIdx.x;
    const int warp = tid >> 5;
    const int lane = tid & 31;
    const int g_   = lane >> 2;      // fragment group
    const int t_   = lane & 3;       // thread-in-group

    // ---- prologue: W fragments (hi, lo) into registers. Warp w: K chunk w*64.
    u32 Ahi[4][4], Alo[4][4];
    {
        const int m0 = g_, m1 = g_ + 8;
        const int row0 = (m0 >> 2) * HH + cta * 4 + (m0 & 3);
        const int row1 = (m1 >> 2) * HH + cta * 4 + (m1 & 3);
        const float* p0 = Whh + (size_t)row0 * HH;
        const float* p1 = Whh + (size_t)row1 * HH;
#pragma unroll
        for (int kt = 0; kt < 4; kt++) {
            int k0 = warp * 64 + kt * 16 + 2 * t_;
            float2 v00 = *(const float2*)(p0 + k0);
            float2 v01 = *(const float2*)(p1 + k0);
            float2 v02 = *(const float2*)(p0 + k0 + 8);
            float2 v03 = *(const float2*)(p1 + k0 + 8);
            float2 vv[4] = {v00, v01, v02, v03};
#pragma unroll
            for (int r = 0; r < 4; r++) {
                float hx = __bfloat162float(__float2bfloat16(vv[r].x));
                float hy = __bfloat162float(__float2bfloat16(vv[r].y));
                Ahi[kt][r] = pack_bf2(vv[r].x, vv[r].y);
                Alo[kt][r] = pack_bf2(vv[r].x - hx, vv[r].y - hy);
            }
        }
    }

    // updater mapping (tid < 128): b = tid>>2, u = tid&3
    const int ub = tid >> 2, uu = tid & 3;
    int   len = 0;
    float c_r = 0.0f, h_r = 0.0f;
    if (tid < 128) len = lengths[ub];

    const int n16 = PLANE_B / 16;    // 2080 16B-chunks per plane

    for (int t = 0; t < TT; t++) {
        const int p = t & 1;

        // xg prefetch (independent of h; in flight during poll)
        float xg0 = 0.f, xg1 = 0.f, xg2 = 0.f, xg3 = 0.f;
        if (tid < 128) {
            const float* xp = g_xp + ((size_t)t * GG + cta * 4 + uu) * BB + ub;
            xg0 = xp[0 * HH * BB];
            xg1 = xp[1 * HH * BB];
            xg2 = xp[2 * HH * BB];
            xg3 = xp[3 * HH * BB];
        }

        // grid barrier: all 128 CTAs published step t-1
        if (t > 0 && tid < NCTA) {
            const unsigned* f = &g_flags[tid * 8];
            unsigned v;
            do {
                asm volatile("ld.acquire.gpu.u32 %0, [%1];" : "=r"(v) : "l"(f) : "memory");
            } while (v < (unsigned)t);
        }
        __syncthreads();

        // stage hi plane (group 0), then lo plane (group 1)
        const unsigned char* shi = g_h[p][0];
        const unsigned char* slo = g_h[p][1];
#pragma unroll
        for (int i = 0; i < 9; i++) {
            int idx = tid + i * 256;
            if (idx < n16) cp_async16(smem_base + SM_HI + idx * 16, shi + idx * 16);
        }
        asm volatile("cp.async.commit_group;" ::: "memory");
#pragma unroll
        for (int i = 0; i < 9; i++) {
            int idx = tid + i * 256;
            if (idx < n16) cp_async16(smem_base + SM_LO + idx * 16, slo + idx * 16);
        }
        asm volatile("cp.async.commit_group;" ::: "memory");

        asm volatile("cp.async.wait_group 1;" ::: "memory");
        __syncthreads();

        // ---- terms 1 & 3: (Whi + Wlo) * h_hi
        float C[4][4];
#pragma unroll
        for (int nt = 0; nt < 4; nt++)
#pragma unroll
            for (int r = 0; r < 4; r++) C[nt][r] = 0.0f;

#pragma unroll
        for (int kt = 0; kt < 4; kt++) {
            const int wbase = warp * 32 + kt * 8 + t_;
#pragma unroll
            for (int nt = 0; nt < 4; nt++) {
                const int n = nt * 8 + g_;
                u32 b0 = hi_w[n * PITCH_W + wbase];
                u32 b1 = hi_w[n * PITCH_W + wbase + 4];
                mma16816(C[nt][0], C[nt][1], C[nt][2], C[nt][3],
                         Ahi[kt][0], Ahi[kt][1], Ahi[kt][2], Ahi[kt][3], b0, b1);
                mma16816(C[nt][0], C[nt][1], C[nt][2], C[nt][3],
                         Alo[kt][0], Alo[kt][1], Alo[kt][2], Alo[kt][3], b0, b1);
            }
        }

        asm volatile("cp.async.wait_group 0;" ::: "memory");
        __syncthreads();

        // ---- term 2: Whi * h_lo
#pragma unroll
        for (int kt = 0; kt < 4; kt++) {
            const int wbase = warp * 32 + kt * 8 + t_;
#pragma unroll
            for (int nt = 0; nt < 4; nt++) {
                const int n = nt * 8 + g_;
                u32 b0 = lo_w[n * PITCH_W + wbase];
                u32 b1 = lo_w[n * PITCH_W + wbase + 4];
                mma16816(C[nt][0], C[nt][1], C[nt][2], C[nt][3],
                         Ahi[kt][0], Ahi[kt][1], Ahi[kt][2], Ahi[kt][3], b0, b1);
            }
        }

        // ---- write k-partials: red[warp][m][40]
        {
            float* rw = red_s + warp * 16 * 40;
#pragma unroll
            for (int nt = 0; nt < 4; nt++) {
                int n = nt * 8 + 2 * t_;
                *(float2*)(rw + g_ * 40 + n)       = make_float2(C[nt][0], C[nt][1]);
                *(float2*)(rw + (g_ + 8) * 40 + n) = make_float2(C[nt][2], C[nt][3]);
            }
        }
        __syncthreads();

        // ---- updaters: reduce 8 k-partials, gates, state update
        float out_val = 0.0f;
        if (tid < 128) {
            float s[4];
#pragma unroll
            for (int gt = 0; gt < 4; gt++) {
                int m = gt * 4 + uu;
                float a0 = 0.f, a1 = 0.f;
#pragma unroll
                for (int w = 0; w < 8; w += 2) {
                    a0 += red_s[(w * 16 + m) * 40 + ub];
                    a1 += red_s[((w + 1) * 16 + m) * 40 + ub];
                }
                s[gt] = a0 + a1;
            }
            float gi_ = sigm(xg0 + s[0]);
            float gf  = sigm(xg1 + s[1]);
            float gg  = tanh_(xg2 + s[2]);
            float go  = sigm(xg3 + s[3]);
            float cn = gf * c_r + gi_ * gg;
            float hn = go * tanh_(cn);
            bool valid = (t < len);
            if (valid) { c_r = cn; h_r = hn; }
            out_val = valid ? hn : 0.0f;

            // publish h hi/lo bf16 into next-phase images
            __nv_bfloat16 hh = __float2bfloat16(h_r);
            float rlo = h_r - __bfloat162float(hh);
            int kk = cta * 4 + uu;
            *(unsigned short*)(g_h[1 - p][0] + (size_t)ub * (PITCH_W * 4) + kk * 2)
                = __bfloat16_as_ushort(hh);
            *(unsigned short*)(g_h[1 - p][1] + (size_t)ub * (PITCH_W * 4) + kk * 2)
                = __bfloat16_as_ushort(__float2bfloat16(rlo));
        }
        __syncthreads();

        // release flag first, then output store (off critical path)
        if (tid == 0) {
            asm volatile("st.release.gpu.u32 [%0], %1;"
                         :: "l"(&g_flags[cta * 8]), "r"((unsigned)(t + 1)) : "memory");
        }
        if (tid < 128) {
            out[((size_t)t * BB + ub) * HH + cta * 4 + uu] = out_val;
        }
    }

    // final hT, cT
    if (tid < 128) {
        size_t base = (size_t)TT * BB * HH;
        out[base + (size_t)ub * HH + cta * 4 + uu] = h_r;
        out[base + (size_t)BB * HH + (size_t)ub * HH + cta * 4 + uu] = c_r;
    }
}

// =========================================================================
extern "C" void kernel_launch(void* const* d_in, const int* in_sizes, int n_in,
                              void* d_out, int out_size) {
    const float* src  = (const float*)d_in[0];
    const int*   lens = (const int*)d_in[1];
    const float* Wih  = (const float*)d_in[2];
    const float* Whh  = (const float*)d_in[3];
    const float* bih  = (const float*)d_in[4];
    const float* bhh  = (const float*)d_in[5];
    float* out = (float*)d_out;

    const int smem_xproj = (256 * WPITCH + 64 * XPITCH) * 4;
    cudaFuncSetAttribute(xproj_kernel, cudaFuncAttributeMaxDynamicSharedMemorySize, smem_xproj);
    cudaFuncSetAttribute(lstm_kernel,  cudaFuncAttributeMaxDynamicSharedMemorySize, SM_TOT);

    dim3 grid(8, 256);
    xproj_kernel<<<grid, 512, smem_xproj>>>(src, Wih, bih, bhh);
    lstm_kernel<<<NCTA, 256, SM_TOT>>>(lens, Whh, out);
}